// round 11
// baseline (speedup 1.0000x reference)
#include <cuda_runtime.h>
#include <cuda_fp16.h>
#include <cstdint>

#define DD 64
#define NMAX 100032
#define NRELMAX 256
#define EMAX 2000000

// bit-cast helpers
__device__ __forceinline__ unsigned h2_as_u32(__half2 h) {
    union { __half2 h; unsigned u; } c; c.h = h; return c.u;
}
__device__ __forceinline__ __half2 u32_as_h2(unsigned u) {
    union { unsigned u; __half2 h; } c; c.u = u; return c.h;
}
__device__ __forceinline__ uint32_t cvt_tf32(float f) {
    uint32_t u;
    asm("cvt.rna.tf32.f32 %0, %1;" : "=r"(u) : "f"(f));
    return u;
}
// m16n8k8 tf32 MMA (sm_80+ PTX, no arch suffix -> legal on sm_100 target)
__device__ __forceinline__ void mma_t(float* d, uint32_t a0, uint32_t a1, uint32_t a2,
                                      uint32_t a3, uint32_t b0, uint32_t b1) {
    asm("mma.sync.aligned.m16n8k8.row.col.f32.tf32.tf32.f32 "
        "{%0,%1,%2,%3}, {%4,%5,%6,%7}, {%8,%9}, {%0,%1,%2,%3};"
        : "+f"(d[0]), "+f"(d[1]), "+f"(d[2]), "+f"(d[3])
        : "r"(a0), "r"(a1), "r"(a2), "r"(a3), "r"(b0), "r"(b1));
}

// Static scratch
__device__ uint4 g_comb[(size_t)NMAX * 16];   // per node: 64 x half2{GE,M} = 256 B
__device__ float g_eg2[NRELMAX * DD];
__device__ int   g_count[NMAX];
__device__ int   g_rowstart[NMAX + 1];
__device__ int   g_cursor[NMAX];
__device__ int   g_blocksum[128];
__device__ int   g_ready;
__device__ unsigned g_csr[EMAX];              // packed (s<<8)|t

// ---------------------------------------------------------------------------
// init: zero counters + ready flag + EG2 = exp(E_gate)
// ---------------------------------------------------------------------------
__global__ void k_init(const float* __restrict__ Eg, int n, int relTotal) {
    int i = blockIdx.x * blockDim.x + threadIdx.x;
    if (i == 0) g_ready = 0;
    if (i < n) g_count[i] = 0;
    if (i < relTotal) g_eg2[i] = __expf(Eg[i]);
}

// ---------------------------------------------------------------------------
// k_tables via mma.sync tf32 (tensor pipe). Unchanged from R10.
// ---------------------------------------------------------------------------
#define XS 68
#define SM_TOTAL (2 * 128 * XS * 4)

__global__ void __launch_bounds__(256) k_tables_mma(
    const float* __restrict__ X, const float* __restrict__ Vp,
    const float* __restrict__ Vg, const float* __restrict__ Bm,
    const float* __restrict__ Bg, int n)
{
    extern __shared__ float smf[];
    float* sX = smf;                 // [128][68]
    float* sW = smf + 128 * XS;      // [128][68]  (row n = column n of [Vp|Vg])
    int tid = threadIdx.x;
    int nodeBase = blockIdx.x * 128;

    {
        const float4* g4 = reinterpret_cast<const float4*>(X);
        for (int i = tid; i < 128 * 16; i += 256) {
            int row = i >> 4, c4 = i & 15;
            float4 v = make_float4(0.f, 0.f, 0.f, 0.f);
            if (nodeBase + row < n) v = __ldg(g4 + (size_t)(nodeBase + row) * 16 + c4);
            float* dst = sX + row * XS + c4 * 4;
            dst[0] = __uint_as_float(cvt_tf32(v.x));
            dst[1] = __uint_as_float(cvt_tf32(v.y));
            dst[2] = __uint_as_float(cvt_tf32(v.z));
            dst[3] = __uint_as_float(cvt_tf32(v.w));
        }
    }
    for (int i = tid; i < 64 * 64; i += 256) {
        int k = i >> 6, c = i & 63;
        sW[c * XS + k]        = __uint_as_float(cvt_tf32(__ldg(Vp + i)));
        sW[(c + 64) * XS + k] = __uint_as_float(cvt_tf32(__ldg(Vg + i)));
    }
    __syncthreads();

    int wid = tid >> 5;
    int lane = tid & 31;
    int group = lane >> 2;
    int tig = lane & 3;
    int r0 = wid * 16 + group;
    int r1 = r0 + 8;

    float acc[16][4];
#pragma unroll
    for (int j = 0; j < 16; j++)
#pragma unroll
        for (int q = 0; q < 4; q++) acc[j][q] = 0.f;

    const uint32_t* uX = reinterpret_cast<const uint32_t*>(sX);
    const uint32_t* uW = reinterpret_cast<const uint32_t*>(sW);

#pragma unroll
    for (int ks = 0; ks < 8; ks++) {
        int k0 = ks * 8;
        uint32_t a0 = uX[r0 * XS + k0 + tig];
        uint32_t a1 = uX[r1 * XS + k0 + tig];
        uint32_t a2 = uX[r0 * XS + k0 + tig + 4];
        uint32_t a3 = uX[r1 * XS + k0 + tig + 4];
#pragma unroll
        for (int nt = 0; nt < 16; nt++) {
            uint32_t b0 = uW[(nt * 8 + group) * XS + k0 + tig];
            uint32_t b1 = uW[(nt * 8 + group) * XS + k0 + tig + 4];
            mma_t(acc[nt], a0, a1, a2, a3, b0, b1);
        }
    }

    int gnode0 = nodeBase + r0;
    int gnode1 = nodeBase + r1;
    uint2* comb2 = reinterpret_cast<uint2*>(g_comb);

#pragma unroll
    for (int j = 0; j < 8; j++) {
        int d0 = j * 8 + 2 * tig;
        int d1 = d0 + 1;
        float bm0 = __ldg(Bm + d0), bm1 = __ldg(Bm + d1);
        float bg0 = __ldg(Bg + d0), bg1 = __ldg(Bg + d1);
        if (gnode0 < n) {
            float m0 = fmaxf(acc[j][0] + bm0, 0.f);
            float m1 = fmaxf(acc[j][1] + bm1, 0.f);
            float e0 = __expf(acc[j + 8][0] + bg0);
            float e1 = __expf(acc[j + 8][1] + bg1);
            uint2 v;
            v.x = h2_as_u32(__floats2half2_rn(e0, m0));
            v.y = h2_as_u32(__floats2half2_rn(e1, m1));
            comb2[(size_t)gnode0 * 32 + (d0 >> 1)] = v;
        }
        if (gnode1 < n) {
            float m0 = fmaxf(acc[j][2] + bm0, 0.f);
            float m1 = fmaxf(acc[j][3] + bm1, 0.f);
            float e0 = __expf(acc[j + 8][2] + bg0);
            float e1 = __expf(acc[j + 8][3] + bg1);
            uint2 v;
            v.x = h2_as_u32(__floats2half2_rn(e0, m0));
            v.y = h2_as_u32(__floats2half2_rn(e1, m1));
            comb2[(size_t)gnode1 * 32 + (d0 >> 1)] = v;
        }
    }
}

// ---------------------------------------------------------------------------
// histogram (vectorized)
// ---------------------------------------------------------------------------
__global__ void k_hist(const int* __restrict__ ridx, int E) {
    int i4 = blockIdx.x * blockDim.x + threadIdx.x;
    int base = i4 * 4;
    if (base + 3 < E) {
        int4 r = __ldg(reinterpret_cast<const int4*>(ridx) + i4);
        atomicAdd(&g_count[r.x], 1);
        atomicAdd(&g_count[r.y], 1);
        atomicAdd(&g_count[r.z], 1);
        atomicAdd(&g_count[r.w], 1);
    } else {
        for (int i = base; i < E; i++) atomicAdd(&g_count[__ldg(ridx + i)], 1);
    }
}

// ---------------------------------------------------------------------------
// single-pass fused scan (replaces scan1/scan2/scan3). All nb<=98 blocks
// resident (2 blocks/SM at 1024 thr); device spin is graph-capture safe.
// ---------------------------------------------------------------------------
__global__ void __launch_bounds__(1024) k_scan_fused(int n, int nb) {
    __shared__ int sd[1024];
    __shared__ int s_prefix;
    int tid = threadIdx.x;
    int i = blockIdx.x * 1024 + tid;
    int v = (i < n) ? g_count[i] : 0;

    // inclusive block scan
    sd[tid] = v;
    __syncthreads();
#pragma unroll
    for (int d = 1; d < 1024; d <<= 1) {
        int t = (tid >= d) ? sd[tid - d] : 0;
        __syncthreads();
        sd[tid] += t;
        __syncthreads();
    }
    int myscan = sd[tid];          // save before sd reuse
    int total = sd[1023];

    if (tid == 0) {
        g_blocksum[blockIdx.x] = total;
        __threadfence();
        atomicAdd(&g_ready, 1);
        while (atomicAdd(&g_ready, 0) < nb) { }
    }
    __syncthreads();

    // parallel prefix over earlier blocks' totals (reuse sd)
    sd[tid] = (tid < 128 && tid < blockIdx.x) ? g_blocksum[tid] : 0;
    __syncthreads();
#pragma unroll
    for (int s = 512; s > 0; s >>= 1) {
        if (tid < s) sd[tid] += sd[tid + s];
        __syncthreads();
    }
    if (tid == 0) s_prefix = sd[0];
    __syncthreads();

    int excl = s_prefix + myscan - v;
    if (i < n) { g_rowstart[i] = excl; g_cursor[i] = excl; }
    if (blockIdx.x == nb - 1 && tid == 1023) g_rowstart[n] = s_prefix + total;
}

// ---------------------------------------------------------------------------
// scatter (vectorized)
// ---------------------------------------------------------------------------
__global__ void k_scatter(const int* __restrict__ sidx, const int* __restrict__ ridx,
                          const int* __restrict__ tidx, int E) {
    int i4 = blockIdx.x * blockDim.x + threadIdx.x;
    int base = i4 * 4;
    if (base + 3 < E) {
        int4 s = __ldg(reinterpret_cast<const int4*>(sidx) + i4);
        int4 r = __ldg(reinterpret_cast<const int4*>(ridx) + i4);
        int4 t = __ldg(reinterpret_cast<const int4*>(tidx) + i4);
        int p0 = atomicAdd(&g_cursor[r.x], 1);
        int p1 = atomicAdd(&g_cursor[r.y], 1);
        int p2 = atomicAdd(&g_cursor[r.z], 1);
        int p3 = atomicAdd(&g_cursor[r.w], 1);
        g_csr[p0] = ((unsigned)s.x << 8) | (unsigned)t.x;
        g_csr[p1] = ((unsigned)s.y << 8) | (unsigned)t.y;
        g_csr[p2] = ((unsigned)s.z << 8) | (unsigned)t.z;
        g_csr[p3] = ((unsigned)s.w << 8) | (unsigned)t.w;
    } else {
        for (int i = base; i < E; i++) {
            int r = __ldg(ridx + i);
            int pos = atomicAdd(&g_cursor[r], 1);
            g_csr[pos] = ((unsigned)__ldg(sidx + i) << 8) | (unsigned)__ldg(tidx + i);
        }
    }
}

// ---------------------------------------------------------------------------
// Accumulate: one 16-lane group per receiver. fp16 gather, fp32 accumulation.
// Full chunks use a static loop (unroll 4 -> MLP); tail is dynamic. Edge
// order identical to R10 -> bitwise-identical math.
// ---------------------------------------------------------------------------
#define ACC_BODY(JJ)                                                            \
    {                                                                           \
        unsigned p = __shfl_sync(mask, pk, gbase + (JJ));                       \
        int s = p >> 8;                                                         \
        int t = p & 255;                                                        \
        uint4 raw = __ldg(&g_comb[(size_t)s * 16 + lane]);                      \
        float4 g = __ldg(reinterpret_cast<const float4*>(g_eg2 + t * DD) + lane); \
        float2 f0 = __half22float2(u32_as_h2(raw.x));                           \
        float2 f1 = __half22float2(u32_as_h2(raw.y));                           \
        float2 f2 = __half22float2(u32_as_h2(raw.z));                           \
        float2 f3 = __half22float2(u32_as_h2(raw.w));                           \
        float t0 = f0.x * g.x;  den.x += t0;  num.x = fmaf(f0.y, t0, num.x);    \
        float t1 = f1.x * g.y;  den.y += t1;  num.y = fmaf(f1.y, t1, num.y);    \
        float t2 = f2.x * g.z;  den.z += t2;  num.z = fmaf(f2.y, t2, num.z);    \
        float t3 = f3.x * g.w;  den.w += t3;  num.w = fmaf(f3.y, t3, num.w);    \
    }

__global__ void __launch_bounds__(256) k_accum(float* __restrict__ out, int n) {
    int gid = (blockIdx.x * 256 + threadIdx.x) >> 4;   // receiver
    if (gid >= n) return;                               // group-uniform
    int lane = threadIdx.x & 15;
    int gbase = (threadIdx.x & 31) & ~15;
    unsigned mask = 0xFFFFu << gbase;

    int beg = __ldg(&g_rowstart[gid]);
    int end = __ldg(&g_rowstart[gid + 1]);
    int full = beg + ((end - beg) & ~15);

    float4 num = make_float4(0.f, 0.f, 0.f, 0.f);
    float4 den = make_float4(0.f, 0.f, 0.f, 0.f);

    for (int chunk = beg; chunk < full; chunk += 16) {
        unsigned pk = __ldg(&g_csr[chunk + lane]);
#pragma unroll 4
        for (int j = 0; j < 16; j++) ACC_BODY(j)
    }
    if (full < end) {
        int m = end - full;
        unsigned pk = 0;
        if (full + lane < end) pk = __ldg(&g_csr[full + lane]);
        for (int j = 0; j < m; j++) ACC_BODY(j)
    }

    float4 o;
    o.x = den.x > 0.f ? num.x / den.x : 0.f;
    o.y = den.y > 0.f ? num.y / den.y : 0.f;
    o.z = den.z > 0.f ? num.z / den.z : 0.f;
    o.w = den.w > 0.f ? num.w / den.w : 0.f;
    *(reinterpret_cast<float4*>(out + (size_t)gid * DD) + lane) = o;
}

// ---------------------------------------------------------------------------
extern "C" void kernel_launch(void* const* d_in, const int* in_sizes, int n_in,
                              void* d_out, int out_size)
{
    const float* X   = (const float*)d_in[0];
    const float* Vp  = (const float*)d_in[1];
    const float* Vg  = (const float*)d_in[2];
    const float* Eg  = (const float*)d_in[3];
    const float* Bm  = (const float*)d_in[4];
    const float* Bg  = (const float*)d_in[5];
    const int* sidx  = (const int*)d_in[6];
    const int* ridx  = (const int*)d_in[7];
    const int* tidx  = (const int*)d_in[8];
    float* out = (float*)d_out;

    int n        = in_sizes[0] / DD;
    int E        = in_sizes[6];
    int relTotal = in_sizes[3];
    int nb       = (n + 1023) / 1024;
    int e4       = (E + 3) / 4;

    cudaFuncSetAttribute(k_tables_mma, cudaFuncAttributeMaxDynamicSharedMemorySize, SM_TOTAL);

    k_init<<<(n + 255) / 256, 256>>>(Eg, n, relTotal);
    k_tables_mma<<<(n + 127) / 128, 256, SM_TOTAL>>>(X, Vp, Vg, Bm, Bg, n);

    k_hist<<<(e4 + 255) / 256, 256>>>(ridx, E);
    k_scan_fused<<<nb, 1024>>>(n, nb);
    k_scatter<<<(e4 + 255) / 256, 256>>>(sidx, ridx, tidx, E);

    long long work = (long long)n * 16;
    k_accum<<<(int)((work + 255) / 256), 256>>>(out, n);
}

// round 12
// speedup vs baseline: 1.0767x; 1.0767x over previous
#include <cuda_runtime.h>
#include <cuda_fp16.h>
#include <cstdint>

#define DD 64
#define NMAX 100032
#define NRELMAX 256
#define EMAX 2000000

// bit-cast helpers
__device__ __forceinline__ unsigned h2_as_u32(__half2 h) {
    union { __half2 h; unsigned u; } c; c.h = h; return c.u;
}
__device__ __forceinline__ __half2 u32_as_h2(unsigned u) {
    union { unsigned u; __half2 h; } c; c.u = u; return c.h;
}
__device__ __forceinline__ uint32_t cvt_tf32(float f) {
    uint32_t u;
    asm("cvt.rna.tf32.f32 %0, %1;" : "=r"(u) : "f"(f));
    return u;
}
__device__ __forceinline__ float tf32r(float f) { return __uint_as_float(cvt_tf32(f)); }

// m16n8k8 tf32 MMA (sm_80+ PTX, no arch suffix -> legal on sm_100 target)
__device__ __forceinline__ void mma_t(float* d, uint32_t a0, uint32_t a1, uint32_t a2,
                                      uint32_t a3, uint32_t b0, uint32_t b1) {
    asm("mma.sync.aligned.m16n8k8.row.col.f32.tf32.tf32.f32 "
        "{%0,%1,%2,%3}, {%4,%5,%6,%7}, {%8,%9}, {%0,%1,%2,%3};"
        : "+f"(d[0]), "+f"(d[1]), "+f"(d[2]), "+f"(d[3])
        : "r"(a0), "r"(a1), "r"(a2), "r"(a3), "r"(b0), "r"(b1));
}

// Static scratch
__device__ uint4 g_comb[(size_t)NMAX * 16];   // per node: 64 x half2{GE,M} = 256 B
__device__ float g_eg2[NRELMAX * DD];
__device__ int   g_count[NMAX];
__device__ int   g_rowstart[NMAX + 1];
__device__ int   g_cursor[NMAX];
__device__ int   g_blocksum[128];
__device__ int   g_ready;
__device__ unsigned g_csr[EMAX];              // packed (s<<8)|t

// ---------------------------------------------------------------------------
// init: zero counters + ready flag + EG2 = exp(E_gate)
// ---------------------------------------------------------------------------
__global__ void k_init(const float* __restrict__ Eg, int n, int relTotal) {
    int i = blockIdx.x * blockDim.x + threadIdx.x;
    if (i == 0) g_ready = 0;
    if (i < n) g_count[i] = 0;
    if (i < relTotal) g_eg2[i] = __expf(Eg[i]);
}

// ---------------------------------------------------------------------------
// k_tables via mma.sync tf32, fragment-packed smem layout.
//   packed float4 at [ks2][row][t] = (e[16ks2+t], +4, +8, +12)
//   -> one LDS.128 per fragment per TWO k-steps. Plane stride 513 float4
//   (bank-conflict-free for the (group,tig) read pattern).
// ---------------------------------------------------------------------------
#define PL 513                       // plane stride in float4 units
#define SM_TOTAL (8 * PL * 16)       // 2 tensors x 4 planes x 513 float4

__global__ void __launch_bounds__(256) k_tables_mma(
    const float* __restrict__ X, const float* __restrict__ Vp,
    const float* __restrict__ Vg, const float* __restrict__ Bm,
    const float* __restrict__ Bg, int n)
{
    extern __shared__ float4 smf4[];
    float4* sXp = smf4;              // [4][513]
    float4* sWp = smf4 + 4 * PL;     // [4][513]
    int tid = threadIdx.x;
    int nodeBase = blockIdx.x * 128;

    // ---- stage X packed: task = (row, ks2) ----
    {
        const float4* g4 = reinterpret_cast<const float4*>(X);
        for (int task = tid; task < 512; task += 256) {
            int r = task >> 2, ks2 = task & 3;
            float4 v0 = make_float4(0.f, 0.f, 0.f, 0.f), v1 = v0, v2 = v0, v3 = v0;
            if (nodeBase + r < n) {
                const float4* src = g4 + (size_t)(nodeBase + r) * 16 + ks2 * 4;
                v0 = __ldg(src); v1 = __ldg(src + 1); v2 = __ldg(src + 2); v3 = __ldg(src + 3);
            }
            float4* dst = sXp + ks2 * PL + r * 4;
            dst[0] = make_float4(tf32r(v0.x), tf32r(v1.x), tf32r(v2.x), tf32r(v3.x));
            dst[1] = make_float4(tf32r(v0.y), tf32r(v1.y), tf32r(v2.y), tf32r(v3.y));
            dst[2] = make_float4(tf32r(v0.z), tf32r(v1.z), tf32r(v2.z), tf32r(v3.z));
            dst[3] = make_float4(tf32r(v0.w), tf32r(v1.w), tf32r(v2.w), tf32r(v3.w));
        }
    }
    // ---- stage W packed: row nn of Wt = column of [Vp|Vg]; task = (nn, ks2) ----
    for (int task = tid; task < 512; task += 256) {
        int nn = task >> 2, ks2 = task & 3;
        const float* src = (nn < 64) ? Vp : Vg;
        int c = nn & 63;
        float e[16];
#pragma unroll
        for (int t = 0; t < 16; t++) e[t] = __ldg(src + (ks2 * 16 + t) * DD + c);
        float4* dst = sWp + ks2 * PL + nn * 4;
        dst[0] = make_float4(tf32r(e[0]), tf32r(e[4]), tf32r(e[8]),  tf32r(e[12]));
        dst[1] = make_float4(tf32r(e[1]), tf32r(e[5]), tf32r(e[9]),  tf32r(e[13]));
        dst[2] = make_float4(tf32r(e[2]), tf32r(e[6]), tf32r(e[10]), tf32r(e[14]));
        dst[3] = make_float4(tf32r(e[3]), tf32r(e[7]), tf32r(e[11]), tf32r(e[15]));
    }
    __syncthreads();

    int wid = tid >> 5;
    int lane = tid & 31;
    int group = lane >> 2;    // 0..7
    int tig = lane & 3;       // 0..3
    int r0 = wid * 16 + group;
    int r1 = r0 + 8;

    float acc[16][4];
#pragma unroll
    for (int j = 0; j < 16; j++)
#pragma unroll
        for (int q = 0; q < 4; q++) acc[j][q] = 0.f;

#pragma unroll
    for (int ks2 = 0; ks2 < 4; ks2++) {
        float4 A0 = sXp[ks2 * PL + r0 * 4 + tig];   // (X[r0][k0+t], +4, +8, +12), k0=16*ks2
        float4 A1 = sXp[ks2 * PL + r1 * 4 + tig];
#pragma unroll
        for (int nt = 0; nt < 16; nt++) {
            float4 B = sWp[ks2 * PL + (nt * 8 + group) * 4 + tig];
            // k-step 2*ks2   : a0=A0.x a1=A1.x a2=A0.y a3=A1.y b0=B.x b1=B.y
            mma_t(acc[nt], __float_as_uint(A0.x), __float_as_uint(A1.x),
                  __float_as_uint(A0.y), __float_as_uint(A1.y),
                  __float_as_uint(B.x), __float_as_uint(B.y));
            // k-step 2*ks2+1 : shifted by 8 in k
            mma_t(acc[nt], __float_as_uint(A0.z), __float_as_uint(A1.z),
                  __float_as_uint(A0.w), __float_as_uint(A1.w),
                  __float_as_uint(B.z), __float_as_uint(B.w));
        }
    }

    int gnode0 = nodeBase + r0;
    int gnode1 = nodeBase + r1;
    uint2* comb2 = reinterpret_cast<uint2*>(g_comb);

#pragma unroll
    for (int j = 0; j < 8; j++) {
        int d0 = j * 8 + 2 * tig;
        int d1 = d0 + 1;
        float bm0 = __ldg(Bm + d0), bm1 = __ldg(Bm + d1);
        float bg0 = __ldg(Bg + d0), bg1 = __ldg(Bg + d1);
        if (gnode0 < n) {
            float m0 = fmaxf(acc[j][0] + bm0, 0.f);
            float m1 = fmaxf(acc[j][1] + bm1, 0.f);
            float e0 = __expf(acc[j + 8][0] + bg0);
            float e1 = __expf(acc[j + 8][1] + bg1);
            uint2 v;
            v.x = h2_as_u32(__floats2half2_rn(e0, m0));
            v.y = h2_as_u32(__floats2half2_rn(e1, m1));
            comb2[(size_t)gnode0 * 32 + (d0 >> 1)] = v;
        }
        if (gnode1 < n) {
            float m0 = fmaxf(acc[j][2] + bm0, 0.f);
            float m1 = fmaxf(acc[j][3] + bm1, 0.f);
            float e0 = __expf(acc[j + 8][2] + bg0);
            float e1 = __expf(acc[j + 8][3] + bg1);
            uint2 v;
            v.x = h2_as_u32(__floats2half2_rn(e0, m0));
            v.y = h2_as_u32(__floats2half2_rn(e1, m1));
            comb2[(size_t)gnode1 * 32 + (d0 >> 1)] = v;
        }
    }
}

// ---------------------------------------------------------------------------
// histogram (vectorized)
// ---------------------------------------------------------------------------
__global__ void k_hist(const int* __restrict__ ridx, int E) {
    int i4 = blockIdx.x * blockDim.x + threadIdx.x;
    int base = i4 * 4;
    if (base + 3 < E) {
        int4 r = __ldg(reinterpret_cast<const int4*>(ridx) + i4);
        atomicAdd(&g_count[r.x], 1);
        atomicAdd(&g_count[r.y], 1);
        atomicAdd(&g_count[r.z], 1);
        atomicAdd(&g_count[r.w], 1);
    } else {
        for (int i = base; i < E; i++) atomicAdd(&g_count[__ldg(ridx + i)], 1);
    }
}

// ---------------------------------------------------------------------------
// single-pass fused scan
// ---------------------------------------------------------------------------
__global__ void __launch_bounds__(1024) k_scan_fused(int n, int nb) {
    __shared__ int sd[1024];
    __shared__ int s_prefix;
    int tid = threadIdx.x;
    int i = blockIdx.x * 1024 + tid;
    int v = (i < n) ? g_count[i] : 0;

    sd[tid] = v;
    __syncthreads();
#pragma unroll
    for (int d = 1; d < 1024; d <<= 1) {
        int t = (tid >= d) ? sd[tid - d] : 0;
        __syncthreads();
        sd[tid] += t;
        __syncthreads();
    }
    int myscan = sd[tid];
    int total = sd[1023];

    if (tid == 0) {
        g_blocksum[blockIdx.x] = total;
        __threadfence();
        atomicAdd(&g_ready, 1);
        while (atomicAdd(&g_ready, 0) < nb) { }
    }
    __syncthreads();

    sd[tid] = (tid < 128 && tid < blockIdx.x) ? g_blocksum[tid] : 0;
    __syncthreads();
#pragma unroll
    for (int s = 512; s > 0; s >>= 1) {
        if (tid < s) sd[tid] += sd[tid + s];
        __syncthreads();
    }
    if (tid == 0) s_prefix = sd[0];
    __syncthreads();

    int excl = s_prefix + myscan - v;
    if (i < n) { g_rowstart[i] = excl; g_cursor[i] = excl; }
    if (blockIdx.x == nb - 1 && tid == 1023) g_rowstart[n] = s_prefix + total;
}

// ---------------------------------------------------------------------------
// scatter (vectorized)
// ---------------------------------------------------------------------------
__global__ void k_scatter(const int* __restrict__ sidx, const int* __restrict__ ridx,
                          const int* __restrict__ tidx, int E) {
    int i4 = blockIdx.x * blockDim.x + threadIdx.x;
    int base = i4 * 4;
    if (base + 3 < E) {
        int4 s = __ldg(reinterpret_cast<const int4*>(sidx) + i4);
        int4 r = __ldg(reinterpret_cast<const int4*>(ridx) + i4);
        int4 t = __ldg(reinterpret_cast<const int4*>(tidx) + i4);
        int p0 = atomicAdd(&g_cursor[r.x], 1);
        int p1 = atomicAdd(&g_cursor[r.y], 1);
        int p2 = atomicAdd(&g_cursor[r.z], 1);
        int p3 = atomicAdd(&g_cursor[r.w], 1);
        g_csr[p0] = ((unsigned)s.x << 8) | (unsigned)t.x;
        g_csr[p1] = ((unsigned)s.y << 8) | (unsigned)t.y;
        g_csr[p2] = ((unsigned)s.z << 8) | (unsigned)t.z;
        g_csr[p3] = ((unsigned)s.w << 8) | (unsigned)t.w;
    } else {
        for (int i = base; i < E; i++) {
            int r = __ldg(ridx + i);
            int pos = atomicAdd(&g_cursor[r], 1);
            g_csr[pos] = ((unsigned)__ldg(sidx + i) << 8) | (unsigned)__ldg(tidx + i);
        }
    }
}

// ---------------------------------------------------------------------------
// Accumulate (unchanged from R11)
// ---------------------------------------------------------------------------
#define ACC_BODY(JJ)                                                            \
    {                                                                           \
        unsigned p = __shfl_sync(mask, pk, gbase + (JJ));                       \
        int s = p >> 8;                                                         \
        int t = p & 255;                                                        \
        uint4 raw = __ldg(&g_comb[(size_t)s * 16 + lane]);                      \
        float4 g = __ldg(reinterpret_cast<const float4*>(g_eg2 + t * DD) + lane); \
        float2 f0 = __half22float2(u32_as_h2(raw.x));                           \
        float2 f1 = __half22float2(u32_as_h2(raw.y));                           \
        float2 f2 = __half22float2(u32_as_h2(raw.z));                           \
        float2 f3 = __half22float2(u32_as_h2(raw.w));                           \
        float t0 = f0.x * g.x;  den.x += t0;  num.x = fmaf(f0.y, t0, num.x);    \
        float t1 = f1.x * g.y;  den.y += t1;  num.y = fmaf(f1.y, t1, num.y);    \
        float t2 = f2.x * g.z;  den.z += t2;  num.z = fmaf(f2.y, t2, num.z);    \
        float t3 = f3.x * g.w;  den.w += t3;  num.w = fmaf(f3.y, t3, num.w);    \
    }

__global__ void __launch_bounds__(256) k_accum(float* __restrict__ out, int n) {
    int gid = (blockIdx.x * 256 + threadIdx.x) >> 4;
    if (gid >= n) return;
    int lane = threadIdx.x & 15;
    int gbase = (threadIdx.x & 31) & ~15;
    unsigned mask = 0xFFFFu << gbase;

    int beg = __ldg(&g_rowstart[gid]);
    int end = __ldg(&g_rowstart[gid + 1]);
    int full = beg + ((end - beg) & ~15);

    float4 num = make_float4(0.f, 0.f, 0.f, 0.f);
    float4 den = make_float4(0.f, 0.f, 0.f, 0.f);

    for (int chunk = beg; chunk < full; chunk += 16) {
        unsigned pk = __ldg(&g_csr[chunk + lane]);
#pragma unroll 4
        for (int j = 0; j < 16; j++) ACC_BODY(j)
    }
    if (full < end) {
        int m = end - full;
        unsigned pk = 0;
        if (full + lane < end) pk = __ldg(&g_csr[full + lane]);
        for (int j = 0; j < m; j++) ACC_BODY(j)
    }

    float4 o;
    o.x = den.x > 0.f ? num.x / den.x : 0.f;
    o.y = den.y > 0.f ? num.y / den.y : 0.f;
    o.z = den.z > 0.f ? num.z / den.z : 0.f;
    o.w = den.w > 0.f ? num.w / den.w : 0.f;
    *(reinterpret_cast<float4*>(out + (size_t)gid * DD) + lane) = o;
}

// ---------------------------------------------------------------------------
extern "C" void kernel_launch(void* const* d_in, const int* in_sizes, int n_in,
                              void* d_out, int out_size)
{
    const float* X   = (const float*)d_in[0];
    const float* Vp  = (const float*)d_in[1];
    const float* Vg  = (const float*)d_in[2];
    const float* Eg  = (const float*)d_in[3];
    const float* Bm  = (const float*)d_in[4];
    const float* Bg  = (const float*)d_in[5];
    const int* sidx  = (const int*)d_in[6];
    const int* ridx  = (const int*)d_in[7];
    const int* tidx  = (const int*)d_in[8];
    float* out = (float*)d_out;

    int n        = in_sizes[0] / DD;
    int E        = in_sizes[6];
    int relTotal = in_sizes[3];
    int nb       = (n + 1023) / 1024;
    int e4       = (E + 3) / 4;

    cudaFuncSetAttribute(k_tables_mma, cudaFuncAttributeMaxDynamicSharedMemorySize, SM_TOTAL);

    k_init<<<(n + 255) / 256, 256>>>(Eg, n, relTotal);
    k_tables_mma<<<(n + 127) / 128, 256, SM_TOTAL>>>(X, Vp, Vg, Bm, Bg, n);

    k_hist<<<(e4 + 255) / 256, 256>>>(ridx, E);
    k_scan_fused<<<nb, 1024>>>(n, nb);
    k_scatter<<<(e4 + 255) / 256, 256>>>(sidx, ridx, tidx, E);

    long long work = (long long)n * 16;
    k_accum<<<(int)((work + 255) / 256), 256>>>(out, n);
}

// round 13
// speedup vs baseline: 1.0795x; 1.0027x over previous
#include <cuda_runtime.h>
#include <cuda_fp16.h>
#include <cstdint>

#define DD 64
#define NMAX 100032
#define NRELMAX 256
#define EMAX 2000000

// bit-cast helpers
__device__ __forceinline__ unsigned h2_as_u32(__half2 h) {
    union { __half2 h; unsigned u; } c; c.h = h; return c.u;
}
__device__ __forceinline__ __half2 u32_as_h2(unsigned u) {
    union { unsigned u; __half2 h; } c; c.u = u; return c.h;
}
__device__ __forceinline__ uint32_t cvt_tf32(float f) {
    uint32_t u;
    asm("cvt.rna.tf32.f32 %0, %1;" : "=r"(u) : "f"(f));
    return u;
}
__device__ __forceinline__ float tf32r(float f) { return __uint_as_float(cvt_tf32(f)); }

// m16n8k8 tf32 MMA (sm_80+ PTX, no arch suffix -> legal on sm_100 target)
__device__ __forceinline__ void mma_t(float* d, uint32_t a0, uint32_t a1, uint32_t a2,
                                      uint32_t a3, uint32_t b0, uint32_t b1) {
    asm("mma.sync.aligned.m16n8k8.row.col.f32.tf32.tf32.f32 "
        "{%0,%1,%2,%3}, {%4,%5,%6,%7}, {%8,%9}, {%0,%1,%2,%3};"
        : "+f"(d[0]), "+f"(d[1]), "+f"(d[2]), "+f"(d[3])
        : "r"(a0), "r"(a1), "r"(a2), "r"(a3), "r"(b0), "r"(b1));
}

// Static scratch
__device__ uint4 g_comb[(size_t)NMAX * 16];   // per node: 64 x half2{GE,M} = 256 B
__device__ float g_eg2[NRELMAX * DD];
__device__ int   g_count[NMAX];
__device__ int   g_rowstart[NMAX + 1];
__device__ int   g_cursor[NMAX];
__device__ int   g_blocksum[128];
__device__ int   g_ready;
__device__ unsigned g_csr[EMAX];              // packed (s<<8)|t

// ---------------------------------------------------------------------------
// init: zero counters (int4) + ready flag + EG2 = exp(E_gate)
// ---------------------------------------------------------------------------
__global__ void k_init(const float* __restrict__ Eg, int n4, int relTotal) {
    int i = blockIdx.x * blockDim.x + threadIdx.x;
    if (i == 0) g_ready = 0;
    if (i < n4) reinterpret_cast<int4*>(g_count)[i] = make_int4(0, 0, 0, 0);
    if (i < relTotal) g_eg2[i] = __expf(Eg[i]);
}

// ---------------------------------------------------------------------------
// k_tables via mma.sync tf32, fragment-packed smem (unchanged from R12).
// ---------------------------------------------------------------------------
#define PL 513
#define SM_TOTAL (8 * PL * 16)

__global__ void __launch_bounds__(256) k_tables_mma(
    const float* __restrict__ X, const float* __restrict__ Vp,
    const float* __restrict__ Vg, const float* __restrict__ Bm,
    const float* __restrict__ Bg, int n)
{
    extern __shared__ float4 smf4[];
    float4* sXp = smf4;              // [4][513]
    float4* sWp = smf4 + 4 * PL;     // [4][513]
    int tid = threadIdx.x;
    int nodeBase = blockIdx.x * 128;

    {
        const float4* g4 = reinterpret_cast<const float4*>(X);
        for (int task = tid; task < 512; task += 256) {
            int r = task >> 2, ks2 = task & 3;
            float4 v0 = make_float4(0.f, 0.f, 0.f, 0.f), v1 = v0, v2 = v0, v3 = v0;
            if (nodeBase + r < n) {
                const float4* src = g4 + (size_t)(nodeBase + r) * 16 + ks2 * 4;
                v0 = __ldg(src); v1 = __ldg(src + 1); v2 = __ldg(src + 2); v3 = __ldg(src + 3);
            }
            float4* dst = sXp + ks2 * PL + r * 4;
            dst[0] = make_float4(tf32r(v0.x), tf32r(v1.x), tf32r(v2.x), tf32r(v3.x));
            dst[1] = make_float4(tf32r(v0.y), tf32r(v1.y), tf32r(v2.y), tf32r(v3.y));
            dst[2] = make_float4(tf32r(v0.z), tf32r(v1.z), tf32r(v2.z), tf32r(v3.z));
            dst[3] = make_float4(tf32r(v0.w), tf32r(v1.w), tf32r(v2.w), tf32r(v3.w));
        }
    }
    for (int task = tid; task < 512; task += 256) {
        int nn = task >> 2, ks2 = task & 3;
        const float* src = (nn < 64) ? Vp : Vg;
        int c = nn & 63;
        float e[16];
#pragma unroll
        for (int t = 0; t < 16; t++) e[t] = __ldg(src + (ks2 * 16 + t) * DD + c);
        float4* dst = sWp + ks2 * PL + nn * 4;
        dst[0] = make_float4(tf32r(e[0]), tf32r(e[4]), tf32r(e[8]),  tf32r(e[12]));
        dst[1] = make_float4(tf32r(e[1]), tf32r(e[5]), tf32r(e[9]),  tf32r(e[13]));
        dst[2] = make_float4(tf32r(e[2]), tf32r(e[6]), tf32r(e[10]), tf32r(e[14]));
        dst[3] = make_float4(tf32r(e[3]), tf32r(e[7]), tf32r(e[11]), tf32r(e[15]));
    }
    __syncthreads();

    int wid = tid >> 5;
    int lane = tid & 31;
    int group = lane >> 2;
    int tig = lane & 3;
    int r0 = wid * 16 + group;
    int r1 = r0 + 8;

    float acc[16][4];
#pragma unroll
    for (int j = 0; j < 16; j++)
#pragma unroll
        for (int q = 0; q < 4; q++) acc[j][q] = 0.f;

#pragma unroll
    for (int ks2 = 0; ks2 < 4; ks2++) {
        float4 A0 = sXp[ks2 * PL + r0 * 4 + tig];
        float4 A1 = sXp[ks2 * PL + r1 * 4 + tig];
#pragma unroll
        for (int nt = 0; nt < 16; nt++) {
            float4 B = sWp[ks2 * PL + (nt * 8 + group) * 4 + tig];
            mma_t(acc[nt], __float_as_uint(A0.x), __float_as_uint(A1.x),
                  __float_as_uint(A0.y), __float_as_uint(A1.y),
                  __float_as_uint(B.x), __float_as_uint(B.y));
            mma_t(acc[nt], __float_as_uint(A0.z), __float_as_uint(A1.z),
                  __float_as_uint(A0.w), __float_as_uint(A1.w),
                  __float_as_uint(B.z), __float_as_uint(B.w));
        }
    }

    int gnode0 = nodeBase + r0;
    int gnode1 = nodeBase + r1;
    uint2* comb2 = reinterpret_cast<uint2*>(g_comb);

#pragma unroll
    for (int j = 0; j < 8; j++) {
        int d0 = j * 8 + 2 * tig;
        int d1 = d0 + 1;
        float bm0 = __ldg(Bm + d0), bm1 = __ldg(Bm + d1);
        float bg0 = __ldg(Bg + d0), bg1 = __ldg(Bg + d1);
        if (gnode0 < n) {
            float m0 = fmaxf(acc[j][0] + bm0, 0.f);
            float m1 = fmaxf(acc[j][1] + bm1, 0.f);
            float e0 = __expf(acc[j + 8][0] + bg0);
            float e1 = __expf(acc[j + 8][1] + bg1);
            uint2 v;
            v.x = h2_as_u32(__floats2half2_rn(e0, m0));
            v.y = h2_as_u32(__floats2half2_rn(e1, m1));
            comb2[(size_t)gnode0 * 32 + (d0 >> 1)] = v;
        }
        if (gnode1 < n) {
            float m0 = fmaxf(acc[j][2] + bm0, 0.f);
            float m1 = fmaxf(acc[j][3] + bm1, 0.f);
            float e0 = __expf(acc[j + 8][2] + bg0);
            float e1 = __expf(acc[j + 8][3] + bg1);
            uint2 v;
            v.x = h2_as_u32(__floats2half2_rn(e0, m0));
            v.y = h2_as_u32(__floats2half2_rn(e1, m1));
            comb2[(size_t)gnode1 * 32 + (d0 >> 1)] = v;
        }
    }
}

// ---------------------------------------------------------------------------
// histogram (vectorized)
// ---------------------------------------------------------------------------
__global__ void k_hist(const int* __restrict__ ridx, int E) {
    int i4 = blockIdx.x * blockDim.x + threadIdx.x;
    int base = i4 * 4;
    if (base + 3 < E) {
        int4 r = __ldg(reinterpret_cast<const int4*>(ridx) + i4);
        atomicAdd(&g_count[r.x], 1);
        atomicAdd(&g_count[r.y], 1);
        atomicAdd(&g_count[r.z], 1);
        atomicAdd(&g_count[r.w], 1);
    } else {
        for (int i = base; i < E; i++) atomicAdd(&g_count[__ldg(ridx + i)], 1);
    }
}

// ---------------------------------------------------------------------------
// single-pass fused scan, shuffle-based (3 barriers total).
// 256 threads x 4 elements = 1024/block; 98 blocks resident.
// ---------------------------------------------------------------------------
__global__ void __launch_bounds__(256) k_scan_fused(int n, int nb) {
    __shared__ int warpsum[8];
    __shared__ int s_prefix;
    int tid = threadIdx.x;
    int lane = tid & 31;
    int wid = tid >> 5;
    int i4 = blockIdx.x * 256 + tid;      // int4 index
    int base = i4 * 4;

    int4 v = make_int4(0, 0, 0, 0);
    if (base + 3 < n) v = *reinterpret_cast<const int4*>(g_count + base);
    else {
        if (base + 0 < n) v.x = g_count[base + 0];
        if (base + 1 < n) v.y = g_count[base + 1];
        if (base + 2 < n) v.z = g_count[base + 2];
        if (base + 3 < n) v.w = g_count[base + 3];
    }
    int tsum = v.x + v.y + v.z + v.w;

    // inclusive warp scan of tsum
    int sc = tsum;
#pragma unroll
    for (int d = 1; d < 32; d <<= 1) {
        int o = __shfl_up_sync(0xffffffffu, sc, d);
        if (lane >= d) sc += o;
    }
    if (lane == 31) warpsum[wid] = sc;
    __syncthreads();

    // warp 0 scans the 8 warp sums; also posts block total + cross-block combine
    if (wid == 0) {
        int ws = (lane < 8) ? warpsum[lane] : 0;
        int wsc = ws;
#pragma unroll
        for (int d = 1; d < 8; d <<= 1) {
            int o = __shfl_up_sync(0xffffffffu, wsc, d);
            if (lane >= d) wsc += o;
        }
        if (lane < 8) warpsum[lane] = wsc - ws;   // exclusive warp offsets
        int total = __shfl_sync(0xffffffffu, wsc, 7);

        if (lane == 0) {
            g_blocksum[blockIdx.x] = total;
            __threadfence();
            atomicAdd(&g_ready, 1);
            while (atomicAdd(&g_ready, 0) < nb) { }
        }
        __syncwarp();
        // prefix of earlier blocks' totals (<=128, 4 per lane)
        int p = 0;
#pragma unroll
        for (int q = 0; q < 4; q++) {
            int b = lane * 4 + q;
            if (b < blockIdx.x) p += g_blocksum[b];
        }
#pragma unroll
        for (int d = 16; d > 0; d >>= 1) p += __shfl_xor_sync(0xffffffffu, p, d);
        if (lane == 0) s_prefix = p;
        if (blockIdx.x == nb - 1 && lane == 0) g_rowstart[n] = p + total;
    }
    __syncthreads();

    int excl = s_prefix + warpsum[wid] + (sc - tsum);   // exclusive at this thread
    int e0 = excl;
    int e1 = e0 + v.x;
    int e2 = e1 + v.y;
    int e3 = e2 + v.z;
    if (base + 3 < n) {
        *reinterpret_cast<int4*>(g_rowstart + base) = make_int4(e0, e1, e2, e3);
        *reinterpret_cast<int4*>(g_cursor + base)   = make_int4(e0, e1, e2, e3);
    } else {
        if (base + 0 < n) { g_rowstart[base + 0] = e0; g_cursor[base + 0] = e0; }
        if (base + 1 < n) { g_rowstart[base + 1] = e1; g_cursor[base + 1] = e1; }
        if (base + 2 < n) { g_rowstart[base + 2] = e2; g_cursor[base + 2] = e2; }
        if (base + 3 < n) { g_rowstart[base + 3] = e3; g_cursor[base + 3] = e3; }
    }
}

// ---------------------------------------------------------------------------
// scatter (vectorized)
// ---------------------------------------------------------------------------
__global__ void k_scatter(const int* __restrict__ sidx, const int* __restrict__ ridx,
                          const int* __restrict__ tidx, int E) {
    int i4 = blockIdx.x * blockDim.x + threadIdx.x;
    int base = i4 * 4;
    if (base + 3 < E) {
        int4 s = __ldg(reinterpret_cast<const int4*>(sidx) + i4);
        int4 r = __ldg(reinterpret_cast<const int4*>(ridx) + i4);
        int4 t = __ldg(reinterpret_cast<const int4*>(tidx) + i4);
        int p0 = atomicAdd(&g_cursor[r.x], 1);
        int p1 = atomicAdd(&g_cursor[r.y], 1);
        int p2 = atomicAdd(&g_cursor[r.z], 1);
        int p3 = atomicAdd(&g_cursor[r.w], 1);
        g_csr[p0] = ((unsigned)s.x << 8) | (unsigned)t.x;
        g_csr[p1] = ((unsigned)s.y << 8) | (unsigned)t.y;
        g_csr[p2] = ((unsigned)s.z << 8) | (unsigned)t.z;
        g_csr[p3] = ((unsigned)s.w << 8) | (unsigned)t.w;
    } else {
        for (int i = base; i < E; i++) {
            int r = __ldg(ridx + i);
            int pos = atomicAdd(&g_cursor[r], 1);
            g_csr[pos] = ((unsigned)__ldg(sidx + i) << 8) | (unsigned)__ldg(tidx + i);
        }
    }
}

// ---------------------------------------------------------------------------
// Accumulate (unchanged from R12)
// ---------------------------------------------------------------------------
#define ACC_BODY(JJ)                                                            \
    {                                                                           \
        unsigned p = __shfl_sync(mask, pk, gbase + (JJ));                       \
        int s = p >> 8;                                                         \
        int t = p & 255;                                                        \
        uint4 raw = __ldg(&g_comb[(size_t)s * 16 + lane]);                      \
        float4 g = __ldg(reinterpret_cast<const float4*>(g_eg2 + t * DD) + lane); \
        float2 f0 = __half22float2(u32_as_h2(raw.x));                           \
        float2 f1 = __half22float2(u32_as_h2(raw.y));                           \
        float2 f2 = __half22float2(u32_as_h2(raw.z));                           \
        float2 f3 = __half22float2(u32_as_h2(raw.w));                           \
        float t0 = f0.x * g.x;  den.x += t0;  num.x = fmaf(f0.y, t0, num.x);    \
        float t1 = f1.x * g.y;  den.y += t1;  num.y = fmaf(f1.y, t1, num.y);    \
        float t2 = f2.x * g.z;  den.z += t2;  num.z = fmaf(f2.y, t2, num.z);    \
        float t3 = f3.x * g.w;  den.w += t3;  num.w = fmaf(f3.y, t3, num.w);    \
    }

__global__ void __launch_bounds__(256) k_accum(float* __restrict__ out, int n) {
    int gid = (blockIdx.x * 256 + threadIdx.x) >> 4;
    if (gid >= n) return;
    int lane = threadIdx.x & 15;
    int gbase = (threadIdx.x & 31) & ~15;
    unsigned mask = 0xFFFFu << gbase;

    int beg = __ldg(&g_rowstart[gid]);
    int end = __ldg(&g_rowstart[gid + 1]);
    int full = beg + ((end - beg) & ~15);

    float4 num = make_float4(0.f, 0.f, 0.f, 0.f);
    float4 den = make_float4(0.f, 0.f, 0.f, 0.f);

    for (int chunk = beg; chunk < full; chunk += 16) {
        unsigned pk = __ldg(&g_csr[chunk + lane]);
#pragma unroll 4
        for (int j = 0; j < 16; j++) ACC_BODY(j)
    }
    if (full < end) {
        int m = end - full;
        unsigned pk = 0;
        if (full + lane < end) pk = __ldg(&g_csr[full + lane]);
        for (int j = 0; j < m; j++) ACC_BODY(j)
    }

    float4 o;
    o.x = den.x > 0.f ? num.x / den.x : 0.f;
    o.y = den.y > 0.f ? num.y / den.y : 0.f;
    o.z = den.z > 0.f ? num.z / den.z : 0.f;
    o.w = den.w > 0.f ? num.w / den.w : 0.f;
    *(reinterpret_cast<float4*>(out + (size_t)gid * DD) + lane) = o;
}

// ---------------------------------------------------------------------------
extern "C" void kernel_launch(void* const* d_in, const int* in_sizes, int n_in,
                              void* d_out, int out_size)
{
    const float* X   = (const float*)d_in[0];
    const float* Vp  = (const float*)d_in[1];
    const float* Vg  = (const float*)d_in[2];
    const float* Eg  = (const float*)d_in[3];
    const float* Bm  = (const float*)d_in[4];
    const float* Bg  = (const float*)d_in[5];
    const int* sidx  = (const int*)d_in[6];
    const int* ridx  = (const int*)d_in[7];
    const int* tidx  = (const int*)d_in[8];
    float* out = (float*)d_out;

    int n        = in_sizes[0] / DD;
    int E        = in_sizes[6];
    int relTotal = in_sizes[3];
    int nb       = (n + 1023) / 1024;     // blocks for scan (256 thr x 4)
    int e4       = (E + 3) / 4;
    int n4       = (n + 3) / 4;

    cudaFuncSetAttribute(k_tables_mma, cudaFuncAttributeMaxDynamicSharedMemorySize, SM_TOTAL);

    int initN = (n4 > relTotal) ? n4 : relTotal;
    k_init<<<(initN + 255) / 256, 256>>>(Eg, n4, relTotal);
    k_tables_mma<<<(n + 127) / 128, 256, SM_TOTAL>>>(X, Vp, Vg, Bm, Bg, n);

    k_hist<<<(e4 + 255) / 256, 256>>>(ridx, E);
    k_scan_fused<<<nb, 256>>>(n, nb);
    k_scatter<<<(e4 + 255) / 256, 256>>>(sidx, ridx, tidx, E);

    long long work = (long long)n * 16;
    k_accum<<<(int)((work + 255) / 256), 256>>>(out, n);
}

// round 16
// speedup vs baseline: 1.1106x; 1.0288x over previous
#include <cuda_runtime.h>
#include <cuda_fp16.h>
#include <cstdint>

#define DD 64
#define NMAX 100032
#define NRELMAX 256
#define EMAX 2000000

// bit-cast helpers
__device__ __forceinline__ unsigned h2_as_u32(__half2 h) {
    union { __half2 h; unsigned u; } c; c.h = h; return c.u;
}
__device__ __forceinline__ __half2 u32_as_h2(unsigned u) {
    union { unsigned u; __half2 h; } c; c.u = u; return c.h;
}
__device__ __forceinline__ uint32_t cvt_tf32(float f) {
    uint32_t u;
    asm("cvt.rna.tf32.f32 %0, %1;" : "=r"(u) : "f"(f));
    return u;
}
__device__ __forceinline__ float tf32r(float f) { return __uint_as_float(cvt_tf32(f)); }

// m16n8k8 tf32 MMA (sm_80+ PTX, no arch suffix -> legal on sm_100 target)
__device__ __forceinline__ void mma_t(float* d, uint32_t a0, uint32_t a1, uint32_t a2,
                                      uint32_t a3, uint32_t b0, uint32_t b1) {
    asm("mma.sync.aligned.m16n8k8.row.col.f32.tf32.tf32.f32 "
        "{%0,%1,%2,%3}, {%4,%5,%6,%7}, {%8,%9}, {%0,%1,%2,%3};"
        : "+f"(d[0]), "+f"(d[1]), "+f"(d[2]), "+f"(d[3])
        : "r"(a0), "r"(a1), "r"(a2), "r"(a3), "r"(b0), "r"(b1));
}

// Static scratch
__device__ uint4 g_comb[(size_t)NMAX * 16];   // per node: 64 x half2{GE,M} = 256 B
__device__ float g_eg2[NRELMAX * DD];
__device__ int   g_count[NMAX];
__device__ int   g_rowstart[NMAX + 1];
__device__ int   g_cursor[NMAX];
__device__ int   g_blocksum[128];
__device__ int   g_ready;
__device__ unsigned g_csr[EMAX];              // packed (s<<8)|t

// ---------------------------------------------------------------------------
// init: zero counters (int4) + ready flag + EG2 = exp(E_gate)
// ---------------------------------------------------------------------------
__global__ void k_init(const float* __restrict__ Eg, int n4, int relTotal) {
    int i = blockIdx.x * blockDim.x + threadIdx.x;
    if (i == 0) g_ready = 0;
    if (i < n4) reinterpret_cast<int4*>(g_count)[i] = make_int4(0, 0, 0, 0);
    if (i < relTotal) g_eg2[i] = __expf(Eg[i]);
}

// ---------------------------------------------------------------------------
// k_tables via mma.sync tf32, fragment-packed smem + FUSED histogram tail.
// ---------------------------------------------------------------------------
#define PL 513
#define SM_TOTAL (8 * PL * 16)

__global__ void __launch_bounds__(256) k_tables_mma(
    const float* __restrict__ X, const float* __restrict__ Vp,
    const float* __restrict__ Vg, const float* __restrict__ Bm,
    const float* __restrict__ Bg, int n,
    const int* __restrict__ ridx, int E, int e4)
{
    extern __shared__ float4 smf4[];
    float4* sXp = smf4;              // [4][513]
    float4* sWp = smf4 + 4 * PL;     // [4][513]
    int tid = threadIdx.x;
    int nodeBase = blockIdx.x * 128;

    {
        const float4* g4 = reinterpret_cast<const float4*>(X);
        for (int task = tid; task < 512; task += 256) {
            int r = task >> 2, ks2 = task & 3;
            float4 v0 = make_float4(0.f, 0.f, 0.f, 0.f), v1 = v0, v2 = v0, v3 = v0;
            if (nodeBase + r < n) {
                const float4* src = g4 + (size_t)(nodeBase + r) * 16 + ks2 * 4;
                v0 = __ldg(src); v1 = __ldg(src + 1); v2 = __ldg(src + 2); v3 = __ldg(src + 3);
            }
            float4* dst = sXp + ks2 * PL + r * 4;
            dst[0] = make_float4(tf32r(v0.x), tf32r(v1.x), tf32r(v2.x), tf32r(v3.x));
            dst[1] = make_float4(tf32r(v0.y), tf32r(v1.y), tf32r(v2.y), tf32r(v3.y));
            dst[2] = make_float4(tf32r(v0.z), tf32r(v1.z), tf32r(v2.z), tf32r(v3.z));
            dst[3] = make_float4(tf32r(v0.w), tf32r(v1.w), tf32r(v2.w), tf32r(v3.w));
        }
    }
    for (int task = tid; task < 512; task += 256) {
        int nn = task >> 2, ks2 = task & 3;
        const float* src = (nn < 64) ? Vp : Vg;
        int c = nn & 63;
        float e[16];
#pragma unroll
        for (int t = 0; t < 16; t++) e[t] = __ldg(src + (ks2 * 16 + t) * DD + c);
        float4* dst = sWp + ks2 * PL + nn * 4;
        dst[0] = make_float4(tf32r(e[0]), tf32r(e[4]), tf32r(e[8]),  tf32r(e[12]));
        dst[1] = make_float4(tf32r(e[1]), tf32r(e[5]), tf32r(e[9]),  tf32r(e[13]));
        dst[2] = make_float4(tf32r(e[2]), tf32r(e[6]), tf32r(e[10]), tf32r(e[14]));
        dst[3] = make_float4(tf32r(e[3]), tf32r(e[7]), tf32r(e[11]), tf32r(e[15]));
    }
    __syncthreads();

    int wid = tid >> 5;
    int lane = tid & 31;
    int group = lane >> 2;
    int tig = lane & 3;
    int r0 = wid * 16 + group;
    int r1 = r0 + 8;

    float acc[16][4];
#pragma unroll
    for (int j = 0; j < 16; j++)
#pragma unroll
        for (int q = 0; q < 4; q++) acc[j][q] = 0.f;

#pragma unroll
    for (int ks2 = 0; ks2 < 4; ks2++) {
        float4 A0 = sXp[ks2 * PL + r0 * 4 + tig];
        float4 A1 = sXp[ks2 * PL + r1 * 4 + tig];
#pragma unroll
        for (int nt = 0; nt < 16; nt++) {
            float4 B = sWp[ks2 * PL + (nt * 8 + group) * 4 + tig];
            mma_t(acc[nt], __float_as_uint(A0.x), __float_as_uint(A1.x),
                  __float_as_uint(A0.y), __float_as_uint(A1.y),
                  __float_as_uint(B.x), __float_as_uint(B.y));
            mma_t(acc[nt], __float_as_uint(A0.z), __float_as_uint(A1.z),
                  __float_as_uint(A0.w), __float_as_uint(A1.w),
                  __float_as_uint(B.z), __float_as_uint(B.w));
        }
    }

    int gnode0 = nodeBase + r0;
    int gnode1 = nodeBase + r1;
    uint2* comb2 = reinterpret_cast<uint2*>(g_comb);

#pragma unroll
    for (int j = 0; j < 8; j++) {
        int d0 = j * 8 + 2 * tig;
        int d1 = d0 + 1;
        float bm0 = __ldg(Bm + d0), bm1 = __ldg(Bm + d1);
        float bg0 = __ldg(Bg + d0), bg1 = __ldg(Bg + d1);
        if (gnode0 < n) {
            float m0 = fmaxf(acc[j][0] + bm0, 0.f);
            float m1 = fmaxf(acc[j][1] + bm1, 0.f);
            float e0 = __expf(acc[j + 8][0] + bg0);
            float e1 = __expf(acc[j + 8][1] + bg1);
            uint2 v;
            v.x = h2_as_u32(__floats2half2_rn(e0, m0));
            v.y = h2_as_u32(__floats2half2_rn(e1, m1));
            comb2[(size_t)gnode0 * 32 + (d0 >> 1)] = v;
        }
        if (gnode1 < n) {
            float m0 = fmaxf(acc[j][2] + bm0, 0.f);
            float m1 = fmaxf(acc[j][3] + bm1, 0.f);
            float e0 = __expf(acc[j + 8][2] + bg0);
            float e1 = __expf(acc[j + 8][3] + bg1);
            uint2 v;
            v.x = h2_as_u32(__floats2half2_rn(e0, m0));
            v.y = h2_as_u32(__floats2half2_rn(e1, m1));
            comb2[(size_t)gnode1 * 32 + (d0 >> 1)] = v;
        }
    }

    // ---- fused histogram tail (no barrier needed) ----
    int gthreads = gridDim.x * 256;
    for (int i4 = blockIdx.x * 256 + tid; i4 < e4; i4 += gthreads) {
        int base = i4 * 4;
        if (base + 3 < E) {
            int4 r = __ldg(reinterpret_cast<const int4*>(ridx) + i4);
            atomicAdd(&g_count[r.x], 1);
            atomicAdd(&g_count[r.y], 1);
            atomicAdd(&g_count[r.z], 1);
            atomicAdd(&g_count[r.w], 1);
        } else {
            for (int i = base; i < E; i++) atomicAdd(&g_count[__ldg(ridx + i)], 1);
        }
    }
}

// ---------------------------------------------------------------------------
// single-pass fused scan, shuffle-based (3 barriers total).
// ---------------------------------------------------------------------------
__global__ void __launch_bounds__(256) k_scan_fused(int n, int nb) {
    __shared__ int warpsum[8];
    __shared__ int s_prefix;
    int tid = threadIdx.x;
    int lane = tid & 31;
    int wid = tid >> 5;
    int i4 = blockIdx.x * 256 + tid;
    int base = i4 * 4;

    int4 v = make_int4(0, 0, 0, 0);
    if (base + 3 < n) v = *reinterpret_cast<const int4*>(g_count + base);
    else {
        if (base + 0 < n) v.x = g_count[base + 0];
        if (base + 1 < n) v.y = g_count[base + 1];
        if (base + 2 < n) v.z = g_count[base + 2];
        if (base + 3 < n) v.w = g_count[base + 3];
    }
    int tsum = v.x + v.y + v.z + v.w;

    int sc = tsum;
#pragma unroll
    for (int d = 1; d < 32; d <<= 1) {
        int o = __shfl_up_sync(0xffffffffu, sc, d);
        if (lane >= d) sc += o;
    }
    if (lane == 31) warpsum[wid] = sc;
    __syncthreads();

    if (wid == 0) {
        int ws = (lane < 8) ? warpsum[lane] : 0;
        int wsc = ws;
#pragma unroll
        for (int d = 1; d < 8; d <<= 1) {
            int o = __shfl_up_sync(0xffffffffu, wsc, d);
            if (lane >= d) wsc += o;
        }
        if (lane < 8) warpsum[lane] = wsc - ws;
        int total = __shfl_sync(0xffffffffu, wsc, 7);

        if (lane == 0) {
            g_blocksum[blockIdx.x] = total;
            __threadfence();
            atomicAdd(&g_ready, 1);
            while (atomicAdd(&g_ready, 0) < nb) { }
        }
        __syncwarp();
        int p = 0;
#pragma unroll
        for (int q = 0; q < 4; q++) {
            int b = lane * 4 + q;
            if (b < blockIdx.x) p += g_blocksum[b];
        }
#pragma unroll
        for (int d = 16; d > 0; d >>= 1) p += __shfl_xor_sync(0xffffffffu, p, d);
        if (lane == 0) s_prefix = p;
        if (blockIdx.x == nb - 1 && lane == 0) g_rowstart[n] = p + total;
    }
    __syncthreads();

    int excl = s_prefix + warpsum[wid] + (sc - tsum);
    int e0 = excl;
    int e1 = e0 + v.x;
    int e2 = e1 + v.y;
    int e3 = e2 + v.z;
    if (base + 3 < n) {
        *reinterpret_cast<int4*>(g_rowstart + base) = make_int4(e0, e1, e2, e3);
        *reinterpret_cast<int4*>(g_cursor + base)   = make_int4(e0, e1, e2, e3);
    } else {
        if (base + 0 < n) { g_rowstart[base + 0] = e0; g_cursor[base + 0] = e0; }
        if (base + 1 < n) { g_rowstart[base + 1] = e1; g_cursor[base + 1] = e1; }
        if (base + 2 < n) { g_rowstart[base + 2] = e2; g_cursor[base + 2] = e2; }
        if (base + 3 < n) { g_rowstart[base + 3] = e3; g_cursor[base + 3] = e3; }
    }
}

// ---------------------------------------------------------------------------
// scatter (vectorized)
// ---------------------------------------------------------------------------
__global__ void k_scatter(const int* __restrict__ sidx, const int* __restrict__ ridx,
                          const int* __restrict__ tidx, int E) {
    int i4 = blockIdx.x * blockDim.x + threadIdx.x;
    int base = i4 * 4;
    if (base + 3 < E) {
        int4 s = __ldg(reinterpret_cast<const int4*>(sidx) + i4);
        int4 r = __ldg(reinterpret_cast<const int4*>(ridx) + i4);
        int4 t = __ldg(reinterpret_cast<const int4*>(tidx) + i4);
        int p0 = atomicAdd(&g_cursor[r.x], 1);
        int p1 = atomicAdd(&g_cursor[r.y], 1);
        int p2 = atomicAdd(&g_cursor[r.z], 1);
        int p3 = atomicAdd(&g_cursor[r.w], 1);
        g_csr[p0] = ((unsigned)s.x << 8) | (unsigned)t.x;
        g_csr[p1] = ((unsigned)s.y << 8) | (unsigned)t.y;
        g_csr[p2] = ((unsigned)s.z << 8) | (unsigned)t.z;
        g_csr[p3] = ((unsigned)s.w << 8) | (unsigned)t.w;
    } else {
        for (int i = base; i < E; i++) {
            int r = __ldg(ridx + i);
            int pos = atomicAdd(&g_cursor[r], 1);
            g_csr[pos] = ((unsigned)__ldg(sidx + i) << 8) | (unsigned)__ldg(tidx + i);
        }
    }
}

// ---------------------------------------------------------------------------
// Accumulate (unchanged)
// ---------------------------------------------------------------------------
#define ACC_BODY(JJ)                                                            \
    {                                                                           \
        unsigned p = __shfl_sync(mask, pk, gbase + (JJ));                       \
        int s = p >> 8;                                                         \
        int t = p & 255;                                                        \
        uint4 raw = __ldg(&g_comb[(size_t)s * 16 + lane]);                      \
        float4 g = __ldg(reinterpret_cast<const float4*>(g_eg2 + t * DD) + lane); \
        float2 f0 = __half22float2(u32_as_h2(raw.x));                           \
        float2 f1 = __half22float2(u32_as_h2(raw.y));                           \
        float2 f2 = __half22float2(u32_as_h2(raw.z));                           \
        float2 f3 = __half22float2(u32_as_h2(raw.w));                           \
        float t0 = f0.x * g.x;  den.x += t0;  num.x = fmaf(f0.y, t0, num.x);    \
        float t1 = f1.x * g.y;  den.y += t1;  num.y = fmaf(f1.y, t1, num.y);    \
        float t2 = f2.x * g.z;  den.z += t2;  num.z = fmaf(f2.y, t2, num.z);    \
        float t3 = f3.x * g.w;  den.w += t3;  num.w = fmaf(f3.y, t3, num.w);    \
    }

__global__ void __launch_bounds__(256) k_accum(float* __restrict__ out, int n) {
    int gid = (blockIdx.x * 256 + threadIdx.x) >> 4;
    if (gid >= n) return;
    int lane = threadIdx.x & 15;
    int gbase = (threadIdx.x & 31) & ~15;
    unsigned mask = 0xFFFFu << gbase;

    int beg = __ldg(&g_rowstart[gid]);
    int end = __ldg(&g_rowstart[gid + 1]);
    int full = beg + ((end - beg) & ~15);

    float4 num = make_float4(0.f, 0.f, 0.f, 0.f);
    float4 den = make_float4(0.f, 0.f, 0.f, 0.f);

    for (int chunk = beg; chunk < full; chunk += 16) {
        unsigned pk = __ldg(&g_csr[chunk + lane]);
#pragma unroll 4
        for (int j = 0; j < 16; j++) ACC_BODY(j)
    }
    if (full < end) {
        int m = end - full;
        unsigned pk = 0;
        if (full + lane < end) pk = __ldg(&g_csr[full + lane]);
        for (int j = 0; j < m; j++) ACC_BODY(j)
    }

    float4 o;
    o.x = den.x > 0.f ? num.x / den.x : 0.f;
    o.y = den.y > 0.f ? num.y / den.y : 0.f;
    o.z = den.z > 0.f ? num.z / den.z : 0.f;
    o.w = den.w > 0.f ? num.w / den.w : 0.f;
    *(reinterpret_cast<float4*>(out + (size_t)gid * DD) + lane) = o;
}

// ---------------------------------------------------------------------------
extern "C" void kernel_launch(void* const* d_in, const int* in_sizes, int n_in,
                              void* d_out, int out_size)
{
    const float* X   = (const float*)d_in[0];
    const float* Vp  = (const float*)d_in[1];
    const float* Vg  = (const float*)d_in[2];
    const float* Eg  = (const float*)d_in[3];
    const float* Bm  = (const float*)d_in[4];
    const float* Bg  = (const float*)d_in[5];
    const int* sidx  = (const int*)d_in[6];
    const int* ridx  = (const int*)d_in[7];
    const int* tidx  = (const int*)d_in[8];
    float* out = (float*)d_out;

    int n        = in_sizes[0] / DD;
    int E        = in_sizes[6];
    int relTotal = in_sizes[3];
    int nb       = (n + 1023) / 1024;
    int e4       = (E + 3) / 4;
    int n4       = (n + 3) / 4;

    cudaFuncSetAttribute(k_tables_mma, cudaFuncAttributeMaxDynamicSharedMemorySize, SM_TOTAL);

    int initN = (n4 > relTotal) ? n4 : relTotal;
    k_init<<<(initN + 255) / 256, 256>>>(Eg, n4, relTotal);
    k_tables_mma<<<(n + 127) / 128, 256, SM_TOTAL>>>(X, Vp, Vg, Bm, Bg, n, ridx, E, e4);

    k_scan_fused<<<nb, 256>>>(n, nb);
    k_scatter<<<(e4 + 255) / 256, 256>>>(sidx, ridx, tidx, E);

    long long work = (long long)n * 16;
    k_accum<<<(int)((work + 255) / 256), 256>>>(out, n);
}